// round 2
// baseline (speedup 1.0000x reference)
#include <cuda_runtime.h>
#include <cuda_bf16.h>
#include <cstdint>
#include <math_constants.h>

#define D        256
#define N_MAX    8192
#define BM       64
#define BN       128
#define SPAD     264   // 256 + 8 halves padding: conflict-free fragment LDS

// Normalized inputs in bf16 (temperature 1/0.5 = 2.0 folded into queries).
__device__ __align__(16) __nv_bfloat16 g_Qn[(size_t)N_MAX * D];
__device__ __align__(16) __nv_bfloat16 g_Kn[(size_t)N_MAX * D];

__device__ __forceinline__ void cp_async16(void* smem_dst, const void* gmem_src) {
    uint32_t s = (uint32_t)__cvta_generic_to_shared(smem_dst);
    asm volatile("cp.async.cg.shared.global [%0], [%1], 16;\n" :: "r"(s), "l"(gmem_src));
}
__device__ __forceinline__ void cp_async_commit() {
    asm volatile("cp.async.commit_group;\n" ::: "memory");
}
__device__ __forceinline__ void cp_async_wait_all() {
    asm volatile("cp.async.wait_group 0;\n" ::: "memory");
}

// ---------------------------------------------------------------------------
// Kernel 1: L2 normalize rows. Block = 256 threads = one row (D=256).
// blocks [0, N)  -> queries (scaled by 2 = 1/temperature)
// blocks [N, 2N) -> keys
// ---------------------------------------------------------------------------
__global__ void normalize_kernel(const float* __restrict__ q,
                                 const float* __restrict__ k, int N) {
    int row   = blockIdx.x;
    bool is_q = row < N;
    int  r    = is_q ? row : row - N;
    const float* src = (is_q ? q : k) + (size_t)r * D;
    __nv_bfloat16* dst = (is_q ? g_Qn : g_Kn) + (size_t)r * D;

    float x  = src[threadIdx.x];
    float ss = x * x;
    #pragma unroll
    for (int o = 16; o > 0; o >>= 1) ss += __shfl_xor_sync(0xffffffffu, ss, o);

    __shared__ float wsum[8];
    if ((threadIdx.x & 31) == 0) wsum[threadIdx.x >> 5] = ss;
    __syncthreads();
    float tot = 0.f;
    #pragma unroll
    for (int i = 0; i < 8; ++i) tot += wsum[i];

    float norm  = sqrtf(tot);
    float scale = 1.0f / fmaxf(norm, 1e-12f);
    if (is_q) scale *= 2.0f;           // fold 1/temperature into queries
    dst[threadIdx.x] = __float2bfloat16(x * scale);
}

// ---------------------------------------------------------------------------
// Kernel 2: fused GEMM (bf16 mma.sync) + online row-logsumexp + diag + mean.
// Grid: N/BM CTAs. CTA: 256 threads = 8 warps, warp grid 2(M) x 4(N),
// warp tile 32x32, mma m16n8k16. CTA covers BM q-rows vs all keys in BN
// tiles, with the B tile double-buffered via cp.async.
// ---------------------------------------------------------------------------
__global__ __launch_bounds__(256, 1)
void infonce_kernel(float* __restrict__ out, int N) {
    extern __shared__ __align__(16) char smem_raw[];
    __nv_bfloat16* As = (__nv_bfloat16*)smem_raw;            // BM * SPAD
    __nv_bfloat16* Bs0 = As + BM * SPAD;                     // BN * SPAD (buf 0)
    __nv_bfloat16* Bs1 = Bs0 + BN * SPAD;                    // BN * SPAD (buf 1)
    float* pm   = (float*)(Bs1 + BN * SPAD);                 // BM*4 partial max
    float* ps   = pm + BM * 4;                               // BM*4 partial sum
    float* pd   = ps + BM * 4;                               // BM*4 partial diag
    float* lsum = pd + BM * 4;                               // BM losses

    const int tid    = threadIdx.x;
    const int lane   = tid & 31;
    const int warp   = tid >> 5;
    const int warp_m = warp >> 2;      // 0..1
    const int warp_n = warp & 3;       // 0..3
    const int row0   = blockIdx.x * BM;

    // --- load A (q tile, resident for whole kernel) ---
    {
        const uint4* src = (const uint4*)(g_Qn + (size_t)row0 * D);
        for (int i = tid; i < BM * 32; i += 256) {           // D/8 = 32 uint4/row
            int r = i >> 5, c = i & 31;
            cp_async16(As + r * SPAD + c * 8, src + r * 32 + c);
        }
    }
    // --- prefetch B tile 0 ---
    {
        const uint4* src = (const uint4*)(g_Kn);
        for (int i = tid; i < BN * 32; i += 256) {
            int r = i >> 5, c = i & 31;
            cp_async16(Bs0 + r * SPAD + c * 8, src + r * 32 + c);
        }
    }
    cp_async_commit();

    float rmax[4], rsum[4], rdiag[4];
    #pragma unroll
    for (int i = 0; i < 4; ++i) { rmax[i] = -CUDART_INF_F; rsum[i] = 0.f; rdiag[i] = 0.f; }

    const int diag_kt = blockIdx.x >> 1;        // key-tile holding our diagonal
    const int a_r     = warp_m * 32 + (lane >> 2);
    const int kcol    = (lane & 3) * 2;
    const int NKT     = N / BN;

    for (int kt = 0; kt < NKT; ++kt) {
        __nv_bfloat16* Bs = (kt & 1) ? Bs1 : Bs0;
        cp_async_wait_all();
        __syncthreads();   // buf(kt) full AND all warps done reading buf(kt^1)

        // --- prefetch next B tile into the other buffer ---
        if (kt + 1 < NKT) {
            __nv_bfloat16* Bnxt = (kt & 1) ? Bs0 : Bs1;
            const uint4* src = (const uint4*)(g_Kn + (size_t)(kt + 1) * BN * D);
            for (int i = tid; i < BN * 32; i += 256) {
                int r = i >> 5, c = i & 31;
                cp_async16(Bnxt + r * SPAD + c * 8, src + r * 32 + c);
            }
        }
        cp_async_commit();

        float acc[2][4][4];
        #pragma unroll
        for (int a = 0; a < 2; ++a)
            #pragma unroll
            for (int b = 0; b < 4; ++b)
                #pragma unroll
                for (int c = 0; c < 4; ++c) acc[a][b][c] = 0.f;

        #pragma unroll
        for (int ks = 0; ks < D / 16; ++ks) {
            uint32_t afr[2][4];
            #pragma unroll
            for (int mt = 0; mt < 2; ++mt) {
                const __nv_bfloat16* ap = As + (a_r + mt * 16) * SPAD + ks * 16 + kcol;
                afr[mt][0] = *(const uint32_t*)(ap);                 // (r,   k0)
                afr[mt][1] = *(const uint32_t*)(ap + 8 * SPAD);      // (r+8, k0)
                afr[mt][2] = *(const uint32_t*)(ap + 8);             // (r,   k0+8)
                afr[mt][3] = *(const uint32_t*)(ap + 8 * SPAD + 8);  // (r+8, k0+8)
            }
            #pragma unroll
            for (int nt = 0; nt < 4; ++nt) {
                const __nv_bfloat16* bp =
                    Bs + (warp_n * 32 + nt * 8 + (lane >> 2)) * SPAD + ks * 16 + kcol;
                uint32_t b0 = *(const uint32_t*)(bp);
                uint32_t b1 = *(const uint32_t*)(bp + 8);
                #pragma unroll
                for (int mt = 0; mt < 2; ++mt) {
                    asm volatile(
                        "mma.sync.aligned.m16n8k16.row.col.f32.bf16.bf16.f32 "
                        "{%0,%1,%2,%3}, {%4,%5,%6,%7}, {%8,%9}, {%0,%1,%2,%3};\n"
                        : "+f"(acc[mt][nt][0]), "+f"(acc[mt][nt][1]),
                          "+f"(acc[mt][nt][2]), "+f"(acc[mt][nt][3])
                        : "r"(afr[mt][0]), "r"(afr[mt][1]),
                          "r"(afr[mt][2]), "r"(afr[mt][3]),
                          "r"(b0), "r"(b1));
                }
            }
        }

        // --- epilogue: online logsumexp over this 128-col tile ---
        const int  col0    = kt * BN + warp_n * 32;
        const bool do_diag = (kt == diag_kt);
        #pragma unroll
        for (int rs = 0; rs < 4; ++rs) {
            const int mt = rs >> 1, hf = rs & 1;
            float tmax = -CUDART_INF_F;
            #pragma unroll
            for (int nt = 0; nt < 4; ++nt)
                tmax = fmaxf(tmax, fmaxf(acc[mt][nt][hf * 2], acc[mt][nt][hf * 2 + 1]));
            tmax = fmaxf(tmax, __shfl_xor_sync(0xffffffffu, tmax, 1));
            tmax = fmaxf(tmax, __shfl_xor_sync(0xffffffffu, tmax, 2));

            float p = 0.f;
            #pragma unroll
            for (int nt = 0; nt < 4; ++nt) {
                p += __expf(acc[mt][nt][hf * 2]     - tmax);
                p += __expf(acc[mt][nt][hf * 2 + 1] - tmax);
            }
            p += __shfl_xor_sync(0xffffffffu, p, 1);
            p += __shfl_xor_sync(0xffffffffu, p, 2);

            if (do_diag) {
                const int grow = row0 + warp_m * 32 + mt * 16 + hf * 8 + (lane >> 2);
                #pragma unroll
                for (int nt = 0; nt < 4; ++nt) {
                    int gc = col0 + nt * 8 + (lane & 3) * 2;
                    if (gc     == grow) rdiag[rs] += acc[mt][nt][hf * 2];
                    if (gc + 1 == grow) rdiag[rs] += acc[mt][nt][hf * 2 + 1];
                }
            }

            float nm = fmaxf(rmax[rs], tmax);
            float so = (rmax[rs] == -CUDART_INF_F) ? 0.f : __expf(rmax[rs] - nm);
            rsum[rs] = rsum[rs] * so + p * __expf(tmax - nm);
            rmax[rs] = nm;
        }
    }

    // --- combine diag across the quad, publish per-(row, warp_n) partials ---
    #pragma unroll
    for (int rs = 0; rs < 4; ++rs) {
        rdiag[rs] += __shfl_xor_sync(0xffffffffu, rdiag[rs], 1);
        rdiag[rs] += __shfl_xor_sync(0xffffffffu, rdiag[rs], 2);
    }
    __syncthreads();
    if ((lane & 3) == 0) {
        #pragma unroll
        for (int rs = 0; rs < 4; ++rs) {
            int lr = warp_m * 32 + (rs >> 1) * 16 + (rs & 1) * 8 + (lane >> 2);
            pm[lr * 4 + warp_n] = rmax[rs];
            ps[lr * 4 + warp_n] = rsum[rs];
            pd[lr * 4 + warp_n] = rdiag[rs];
        }
    }
    __syncthreads();

    // --- per-row final: combine 4 n-warp partials, loss = lse - diag ---
    if (tid < BM) {
        float m = pm[tid * 4];
        #pragma unroll
        for (int w = 1; w < 4; ++w) m = fmaxf(m, pm[tid * 4 + w]);
        float s = 0.f, d = 0.f;
        #pragma unroll
        for (int w = 0; w < 4; ++w) {
            s += ps[tid * 4 + w] * __expf(pm[tid * 4 + w] - m);
            d += pd[tid * 4 + w];
        }
        lsum[tid] = logf(s) + m - d;
    }
    __syncthreads();
    if (tid == 0) {
        float t = 0.f;
        for (int i = 0; i < BM; ++i) t += lsum[i];
        atomicAdd(out, t / (float)N);
    }
}

// ---------------------------------------------------------------------------
extern "C" void kernel_launch(void* const* d_in, const int* in_sizes, int n_in,
                              void* d_out, int out_size) {
    const float* q = (const float*)d_in[0];
    const float* k = (const float*)d_in[1];
    const int N = in_sizes[0] / D;      // 8192
    float* out = (float*)d_out;

    // graph replays accumulate via atomicAdd -> re-zero every call
    cudaMemsetAsync(out, 0, sizeof(float), 0);

    normalize_kernel<<<2 * N, D>>>(q, k, N);

    size_t smem = (size_t)(BM + 2 * BN) * SPAD * sizeof(__nv_bfloat16)
                + (size_t)(3 * BM * 4 + BM) * sizeof(float);
    cudaFuncSetAttribute(infonce_kernel,
                         cudaFuncAttributeMaxDynamicSharedMemorySize, (int)smem);
    infonce_kernel<<<N / BM, 256, smem>>>(out, N);
}

// round 4
// speedup vs baseline: 1.0857x; 1.0857x over previous
#include <cuda_runtime.h>
#include <cuda_bf16.h>
#include <cstdint>

#define D        256
#define NMAX     8192
#define BM       64
#define BN       64
#define KSPLIT   2
#define NKEYS    (NMAX / KSPLIT)     // 4096 keys per CTA
#define NT       (NKEYS / BN)        // 64 key tiles
#define GRID_SZ  ((NMAX / BM) * KSPLIT)  // 256 CTAs -> one wave at occ 2
#define SPAD     264                 // 256 + 8 halves pad: conflict-free LDSM

#define LOG2E    1.4426950408889634f
#define LN2      0.6931471805599453f

__device__ __align__(16) __nv_bfloat16 g_Qn[(size_t)NMAX * D];
__device__ __align__(16) __nv_bfloat16 g_Kn[(size_t)NMAX * D];
__device__ float g_psum[NMAX * KSPLIT];
__device__ float g_pdiag[NMAX * KSPLIT];

// ---------------- helpers ----------------
__device__ __forceinline__ void cp_async16(void* smem_dst, const void* gmem_src) {
    uint32_t s = (uint32_t)__cvta_generic_to_shared(smem_dst);
    asm volatile("cp.async.cg.shared.global [%0], [%1], 16;\n" :: "r"(s), "l"(gmem_src));
}
__device__ __forceinline__ void cp_commit() {
    asm volatile("cp.async.commit_group;\n" ::: "memory");
}
__device__ __forceinline__ void cp_wait_all() {
    asm volatile("cp.async.wait_group 0;\n" ::: "memory");
}
__device__ __forceinline__ void ldsm_x4(uint32_t& r0, uint32_t& r1,
                                        uint32_t& r2, uint32_t& r3, uint32_t addr) {
    asm volatile("ldmatrix.sync.aligned.m8n8.x4.shared.b16 {%0,%1,%2,%3}, [%4];"
                 : "=r"(r0), "=r"(r1), "=r"(r2), "=r"(r3) : "r"(addr));
}
__device__ __forceinline__ float exp2_fast(float x) {
    float r;
    asm("ex2.approx.ftz.f32 %0, %1;" : "=f"(r) : "f"(x));
    return r;
}

// Load one [64 x 256 bf16] tile into SPAD-padded smem via cp.async.
__device__ __forceinline__ void load_tile_async(__nv_bfloat16* s,
                                                const __nv_bfloat16* g, int tid) {
    const uint4* src = (const uint4*)g;
    #pragma unroll
    for (int i = tid; i < BM * 32; i += 256) {   // 32 x 16B chunks per row
        int r = i >> 5, c = i & 31;
        cp_async16(s + r * SPAD + c * 8, src + r * 32 + c);
    }
}

// ---------------------------------------------------------------------------
// Kernel 1: L2 normalize rows; queries get 2*log2(e) folded in so logits are
// in log2 domain (|logit| <= 2.89 -> no max tracking needed anywhere).
// ---------------------------------------------------------------------------
__global__ void normalize_kernel(const float* __restrict__ q,
                                 const float* __restrict__ k, int N) {
    int row   = blockIdx.x;
    bool is_q = row < N;
    int  r    = is_q ? row : row - N;
    const float* src = (is_q ? q : k) + (size_t)r * D;
    __nv_bfloat16* dst = (is_q ? g_Qn : g_Kn) + (size_t)r * D;

    float x  = src[threadIdx.x];
    float ss = x * x;
    #pragma unroll
    for (int o = 16; o > 0; o >>= 1) ss += __shfl_xor_sync(0xffffffffu, ss, o);

    __shared__ float wsum[8];
    if ((threadIdx.x & 31) == 0) wsum[threadIdx.x >> 5] = ss;
    __syncthreads();
    float tot = 0.f;
    #pragma unroll
    for (int i = 0; i < 8; ++i) tot += wsum[i];

    float scale = 1.0f / fmaxf(sqrtf(tot), 1e-12f);
    if (is_q) scale *= 2.0f * LOG2E;    // 1/temperature + log2 domain
    dst[threadIdx.x] = __float2bfloat16(x * scale);
}

// ---------------------------------------------------------------------------
// Kernel 2: bf16 mma.sync GEMM + fused sum(2^logit). 256 thr, 2 CTAs/SM.
// Warp grid 2(M) x 4(N); warp tile 32x16; mma m16n8k16, ldmatrix fragments.
// ---------------------------------------------------------------------------
__global__ __launch_bounds__(256, 2)
void infonce_kernel() {
    extern __shared__ __align__(16) char smem_raw[];
    __nv_bfloat16* As  = (__nv_bfloat16*)smem_raw;   // 64 * SPAD
    __nv_bfloat16* Bs0 = As + BM * SPAD;             // 64 * SPAD (buf 0)
    __nv_bfloat16* Bs1 = Bs0 + BN * SPAD;            // 64 * SPAD (buf 1)

    const int tid    = threadIdx.x;
    const int lane   = tid & 31;
    const int warp   = tid >> 5;
    const int warp_m = warp >> 2;       // 0..1 (32 rows each)
    const int warp_n = warp & 3;        // 0..3 (16 cols each)

    const int qb    = blockIdx.x / KSPLIT;
    const int split = blockIdx.x % KSPLIT;
    const int qr0   = qb * BM;
    const int kv0   = split * NKEYS;

    // prologue loads
    load_tile_async(As, g_Qn + (size_t)qr0 * D, tid);
    load_tile_async(Bs0, g_Kn + (size_t)kv0 * D, tid);
    cp_commit();

    // ldmatrix source addresses (bytes into shared space)
    //  A (x4, per mt): rows lane&15, k-half lane>>4
    uint32_t a_base[2];
    #pragma unroll
    for (int mt = 0; mt < 2; ++mt)
        a_base[mt] = (uint32_t)__cvta_generic_to_shared(
            As + (warp_m * 32 + mt * 16 + (lane & 15)) * SPAD + (lane >> 4) * 8);
    //  B (x4 covers nt=0,1): n-row = wn*16 + ((lane>>4)&1)*8 + (lane&7),
    //  k-half = (lane>>3)&1
    const uint32_t b_row_off = (uint32_t)(
        ((warp_n * 16 + ((lane >> 4) & 1) * 8 + (lane & 7)) * SPAD
         + ((lane >> 3) & 1) * 8) * sizeof(__nv_bfloat16));

    const bool cta_has_diag = (qr0 >= kv0) && (qr0 < kv0 + NKEYS);
    const int  kt_diag      = (qr0 - kv0) >> 6;

    float rsum[4]  = {0.f, 0.f, 0.f, 0.f};   // per owned-row 2^logit sums
    float rdiag[4] = {0.f, 0.f, 0.f, 0.f};

    for (int kt = 0; kt < NT; ++kt) {
        __nv_bfloat16* Bs = (kt & 1) ? Bs1 : Bs0;
        cp_wait_all();
        __syncthreads();            // tile kt resident; all warps done with kt-1

        if (kt + 1 < NT)
            load_tile_async((kt & 1) ? Bs0 : Bs1,
                            g_Kn + (size_t)(kv0 + (kt + 1) * BN) * D, tid);
        cp_commit();

        float acc[2][2][4];
        #pragma unroll
        for (int a = 0; a < 2; ++a)
            #pragma unroll
            for (int b = 0; b < 2; ++b)
                #pragma unroll
                for (int c = 0; c < 4; ++c) acc[a][b][c] = 0.f;

        const uint32_t b_base = (uint32_t)__cvta_generic_to_shared(Bs) + b_row_off;

        #pragma unroll
        for (int ks = 0; ks < D / 16; ++ks) {
            uint32_t af[2][4], bf[4];
            ldsm_x4(af[0][0], af[0][1], af[0][2], af[0][3], a_base[0] + ks * 32);
            ldsm_x4(af[1][0], af[1][1], af[1][2], af[1][3], a_base[1] + ks * 32);
            ldsm_x4(bf[0], bf[1], bf[2], bf[3], b_base + ks * 32);
            #pragma unroll
            for (int mt = 0; mt < 2; ++mt)
                #pragma unroll
                for (int nt = 0; nt < 2; ++nt) {
                    asm volatile(
                        "mma.sync.aligned.m16n8k16.row.col.f32.bf16.bf16.f32 "
                        "{%0,%1,%2,%3}, {%4,%5,%6,%7}, {%8,%9}, {%0,%1,%2,%3};\n"
                        : "+f"(acc[mt][nt][0]), "+f"(acc[mt][nt][1]),
                          "+f"(acc[mt][nt][2]), "+f"(acc[mt][nt][3])
                        : "r"(af[mt][0]), "r"(af[mt][1]),
                          "r"(af[mt][2]), "r"(af[mt][3]),
                          "r"(bf[nt * 2]), "r"(bf[nt * 2 + 1]));
                }
        }

        // epilogue: 16 ex2 + adds (no max needed in log2 domain)
        #pragma unroll
        for (int mt = 0; mt < 2; ++mt)
            #pragma unroll
            for (int nt = 0; nt < 2; ++nt)
                #pragma unroll
                for (int c = 0; c < 4; ++c)
                    rsum[mt * 2 + (c >> 1)] += exp2_fast(acc[mt][nt][c]);

        if (cta_has_diag && kt == kt_diag) {
            #pragma unroll
            for (int mt = 0; mt < 2; ++mt)
                #pragma unroll
                for (int nt = 0; nt < 2; ++nt)
                    #pragma unroll
                    for (int c = 0; c < 4; ++c) {
                        int lr = warp_m * 32 + mt * 16 + (c >> 1) * 8 + (lane >> 2);
                        int lc = warp_n * 16 + nt * 8 + (lane & 3) * 2 + (c & 1);
                        if (lr == lc) rdiag[mt * 2 + (c >> 1)] += acc[mt][nt][c];
                    }
        }
    }

    // reduce: 4 lanes of a quad share each row; then 4 n-warps per row via smem
    #pragma unroll
    for (int rs = 0; rs < 4; ++rs) {
        rsum[rs]  += __shfl_xor_sync(0xffffffffu, rsum[rs], 1);
        rsum[rs]  += __shfl_xor_sync(0xffffffffu, rsum[rs], 2);
        rdiag[rs] += __shfl_xor_sync(0xffffffffu, rdiag[rs], 1);
        rdiag[rs] += __shfl_xor_sync(0xffffffffu, rdiag[rs], 2);
    }
    __syncthreads();                       // B buffers free now
    float* s_sum = (float*)Bs0;            // [BM][4]
    float* s_dg  = s_sum + BM * 4;
    if ((lane & 3) == 0) {
        #pragma unroll
        for (int rs = 0; rs < 4; ++rs) {
            int lr = warp_m * 32 + (rs >> 1) * 16 + (rs & 1) * 8 + (lane >> 2);
            s_sum[lr * 4 + warp_n] = rsum[rs];
            s_dg [lr * 4 + warp_n] = rdiag[rs];
        }
    }
    __syncthreads();
    if (tid < BM) {
        float s = 0.f, d = 0.f;
        #pragma unroll
        for (int w = 0; w < 4; ++w) { s += s_sum[tid * 4 + w]; d += s_dg[tid * 4 + w]; }
        int gr = qr0 + tid;
        g_psum [gr * KSPLIT + split] = s;
        g_pdiag[gr * KSPLIT + split] = d;
    }
}

// ---------------------------------------------------------------------------
// Kernel 3: finalize. loss = mean( ln2 * (log2(sum splits) - diag_log2) )
// ---------------------------------------------------------------------------
__global__ void finalize_kernel(float* __restrict__ out) {
    __shared__ float wsum[8];
    float acc = 0.f;
    for (int r = threadIdx.x; r < NMAX; r += 256) {
        float s = 0.f, d = 0.f;
        #pragma unroll
        for (int k = 0; k < KSPLIT; ++k) {
            s += g_psum [r * KSPLIT + k];
            d += g_pdiag[r * KSPLIT + k];
        }
        acc += LN2 * (log2f(s) - d);
    }
    #pragma unroll
    for (int o = 16; o > 0; o >>= 1) acc += __shfl_xor_sync(0xffffffffu, acc, o);
    if ((threadIdx.x & 31) == 0) wsum[threadIdx.x >> 5] = acc;
    __syncthreads();
    if (threadIdx.x == 0) {
        float t = 0.f;
        #pragma unroll
        for (int i = 0; i < 8; ++i) t += wsum[i];
        out[0] = t / (float)NMAX;
    }
}

// ---------------------------------------------------------------------------
extern "C" void kernel_launch(void* const* d_in, const int* in_sizes, int n_in,
                              void* d_out, int out_size) {
    const float* q = (const float*)d_in[0];
    const float* k = (const float*)d_in[1];
    const int N = in_sizes[0] / D;          // 8192
    float* out = (float*)d_out;

    normalize_kernel<<<2 * N, D>>>(q, k, N);

    size_t smem = (size_t)(BM + 2 * BN) * SPAD * sizeof(__nv_bfloat16);
    cudaFuncSetAttribute(infonce_kernel,
                         cudaFuncAttributeMaxDynamicSharedMemorySize, (int)smem);
    infonce_kernel<<<GRID_SZ, 256, smem>>>();

    finalize_kernel<<<1, 256>>>(out);
}

// round 5
// speedup vs baseline: 1.5348x; 1.4137x over previous
#include <cuda_runtime.h>
#include <cuda_bf16.h>
#include <cstdint>

#define D        256
#define NMAX     8192
#define BM       128
#define BN       128
#define KSPLIT   2
#define NKEYS    (NMAX / KSPLIT)         // 4096 keys per CTA
#define NT       (NKEYS / BN)            // 32 key tiles
#define GRID_SZ  ((NMAX / BM) * KSPLIT)  // 128 CTAs, one wave
#define THREADS  512
#define SPAD     264                     // 256 + 8 halves pad: conflict-free LDSM

#define LOG2E    1.4426950408889634f
#define LN2      0.6931471805599453f

__device__ __align__(16) __nv_bfloat16 g_Qn[(size_t)NMAX * D];
__device__ __align__(16) __nv_bfloat16 g_Kn[(size_t)NMAX * D];
__device__ float g_psum[NMAX * KSPLIT];
__device__ float g_pdiag[NMAX * KSPLIT];

// ---------------- helpers ----------------
__device__ __forceinline__ void cp_async16(void* smem_dst, const void* gmem_src) {
    uint32_t s = (uint32_t)__cvta_generic_to_shared(smem_dst);
    asm volatile("cp.async.cg.shared.global [%0], [%1], 16;\n" :: "r"(s), "l"(gmem_src));
}
__device__ __forceinline__ void cp_commit() {
    asm volatile("cp.async.commit_group;\n" ::: "memory");
}
__device__ __forceinline__ void cp_wait_all() {
    asm volatile("cp.async.wait_group 0;\n" ::: "memory");
}
__device__ __forceinline__ void ldsm_x4(uint32_t& r0, uint32_t& r1,
                                        uint32_t& r2, uint32_t& r3, uint32_t addr) {
    asm volatile("ldmatrix.sync.aligned.m8n8.x4.shared.b16 {%0,%1,%2,%3}, [%4];"
                 : "=r"(r0), "=r"(r1), "=r"(r2), "=r"(r3) : "r"(addr));
}
__device__ __forceinline__ float exp2_fast(float x) {
    float r;
    asm("ex2.approx.ftz.f32 %0, %1;" : "=f"(r) : "f"(x));
    return r;
}

// Load one [128 x 256 bf16] tile into SPAD-padded smem via cp.async (512 thr).
__device__ __forceinline__ void load_tile_async(__nv_bfloat16* s,
                                                const __nv_bfloat16* g, int tid) {
    const uint4* src = (const uint4*)g;
    #pragma unroll
    for (int i = tid; i < BM * 32; i += THREADS) {   // 32 x 16B chunks per row
        int r = i >> 5, c = i & 31;
        cp_async16(s + r * SPAD + c * 8, src + r * 32 + c);
    }
}

// ---------------------------------------------------------------------------
// Kernel 1: L2 normalize; one warp per row; queries get 2*log2(e) folded in
// (log2-domain logits, |logit| <= 2.89 -> no max tracking anywhere).
// ---------------------------------------------------------------------------
__global__ void normalize_kernel(const float* __restrict__ q,
                                 const float* __restrict__ k, int N) {
    const int warp = threadIdx.x >> 5, lane = threadIdx.x & 31;
    const int row  = blockIdx.x * 8 + warp;          // grid = 2N/8
    const bool is_q = row < N;
    const int  r    = is_q ? row : row - N;
    const float4* src = (const float4*)((is_q ? q : k) + (size_t)r * D);
    uint4* dst = (uint4*)((is_q ? g_Qn : g_Kn) + (size_t)r * D);

    float4 v0 = src[lane * 2], v1 = src[lane * 2 + 1];
    float ss = v0.x*v0.x + v0.y*v0.y + v0.z*v0.z + v0.w*v0.w
             + v1.x*v1.x + v1.y*v1.y + v1.z*v1.z + v1.w*v1.w;
    #pragma unroll
    for (int o = 16; o > 0; o >>= 1) ss += __shfl_xor_sync(0xffffffffu, ss, o);

    float scale = rsqrtf(fmaxf(ss, 1e-24f));
    if (is_q) scale *= 2.0f * LOG2E;    // 1/temperature + log2 domain

    __nv_bfloat162 b0 = __float22bfloat162_rn({v0.x*scale, v0.y*scale});
    __nv_bfloat162 b1 = __float22bfloat162_rn({v0.z*scale, v0.w*scale});
    __nv_bfloat162 b2 = __float22bfloat162_rn({v1.x*scale, v1.y*scale});
    __nv_bfloat162 b3 = __float22bfloat162_rn({v1.z*scale, v1.w*scale});
    uint4 o;
    o.x = *(uint32_t*)&b0; o.y = *(uint32_t*)&b1;
    o.z = *(uint32_t*)&b2; o.w = *(uint32_t*)&b3;
    dst[lane] = o;
}

// ---------------------------------------------------------------------------
// Kernel 2: bf16 mma.sync GEMM + fused sum(2^logit). 512 thr (16 warps),
// warp grid 4(M) x 4(N), warp tile 32x32, mma m16n8k16 via ldmatrix.
// CTA = 128 q-rows x 4096 keys in 32 double-buffered 128-key tiles.
// ---------------------------------------------------------------------------
__global__ __launch_bounds__(THREADS, 1)
void infonce_kernel() {
    extern __shared__ __align__(16) char smem_raw[];
    __nv_bfloat16* As  = (__nv_bfloat16*)smem_raw;   // 128 * SPAD
    __nv_bfloat16* Bs0 = As + BM * SPAD;             // 128 * SPAD (buf 0)
    __nv_bfloat16* Bs1 = Bs0 + BN * SPAD;            // 128 * SPAD (buf 1)

    const int tid    = threadIdx.x;
    const int lane   = tid & 31;
    const int warp   = tid >> 5;
    const int warp_m = warp >> 2;       // 0..3 (32 rows each)
    const int warp_n = warp & 3;        // 0..3 (32 cols each)

    const int qb    = blockIdx.x / KSPLIT;
    const int split = blockIdx.x % KSPLIT;
    const int qr0   = qb * BM;
    const int kv0   = split * NKEYS;

    // prologue loads
    load_tile_async(As, g_Qn + (size_t)qr0 * D, tid);
    load_tile_async(Bs0, g_Kn + (size_t)kv0 * D, tid);
    cp_commit();

    // ldmatrix addresses
    uint32_t a_base[2];
    #pragma unroll
    for (int mt = 0; mt < 2; ++mt)
        a_base[mt] = (uint32_t)__cvta_generic_to_shared(
            As + (warp_m * 32 + mt * 16 + (lane & 15)) * SPAD + (lane >> 4) * 8);
    uint32_t b_row_off[2];
    #pragma unroll
    for (int b = 0; b < 2; ++b)
        b_row_off[b] = (uint32_t)(
            ((warp_n * 32 + b * 16 + ((lane >> 4) & 1) * 8 + (lane & 7)) * SPAD
             + ((lane >> 3) & 1) * 8) * sizeof(__nv_bfloat16));

    const bool cta_has_diag = (qr0 >= kv0) && (qr0 < kv0 + NKEYS);
    const int  kt_diag      = (qr0 - kv0) >> 7;

    float rsum[4]  = {0.f, 0.f, 0.f, 0.f};
    float rdiag[4] = {0.f, 0.f, 0.f, 0.f};

    for (int kt = 0; kt < NT; ++kt) {
        __nv_bfloat16* Bs = (kt & 1) ? Bs1 : Bs0;
        cp_wait_all();
        __syncthreads();            // tile kt resident; all warps done with kt-1

        if (kt + 1 < NT)
            load_tile_async((kt & 1) ? Bs0 : Bs1,
                            g_Kn + (size_t)(kv0 + (kt + 1) * BN) * D, tid);
        cp_commit();

        float acc[2][4][4];
        #pragma unroll
        for (int a = 0; a < 2; ++a)
            #pragma unroll
            for (int b = 0; b < 4; ++b)
                #pragma unroll
                for (int c = 0; c < 4; ++c) acc[a][b][c] = 0.f;

        const uint32_t bb = (uint32_t)__cvta_generic_to_shared(Bs);

        #pragma unroll
        for (int ks = 0; ks < D / 16; ++ks) {
            uint32_t af[2][4], bf[8];
            ldsm_x4(af[0][0], af[0][1], af[0][2], af[0][3], a_base[0] + ks * 32);
            ldsm_x4(af[1][0], af[1][1], af[1][2], af[1][3], a_base[1] + ks * 32);
            ldsm_x4(bf[0], bf[1], bf[2], bf[3], bb + b_row_off[0] + ks * 32);
            ldsm_x4(bf[4], bf[5], bf[6], bf[7], bb + b_row_off[1] + ks * 32);
            #pragma unroll
            for (int mt = 0; mt < 2; ++mt)
                #pragma unroll
                for (int nt = 0; nt < 4; ++nt) {
                    asm volatile(
                        "mma.sync.aligned.m16n8k16.row.col.f32.bf16.bf16.f32 "
                        "{%0,%1,%2,%3}, {%4,%5,%6,%7}, {%8,%9}, {%0,%1,%2,%3};\n"
                        : "+f"(acc[mt][nt][0]), "+f"(acc[mt][nt][1]),
                          "+f"(acc[mt][nt][2]), "+f"(acc[mt][nt][3])
                        : "r"(af[mt][0]), "r"(af[mt][1]),
                          "r"(af[mt][2]), "r"(af[mt][3]),
                          "r"(bf[nt * 2]), "r"(bf[nt * 2 + 1]));
                }
        }

        // epilogue: 32 ex2 + adds (no max needed in log2 domain)
        #pragma unroll
        for (int mt = 0; mt < 2; ++mt)
            #pragma unroll
            for (int nt = 0; nt < 4; ++nt)
                #pragma unroll
                for (int c = 0; c < 4; ++c)
                    rsum[mt * 2 + (c >> 1)] += exp2_fast(acc[mt][nt][c]);

        if (cta_has_diag && kt == kt_diag) {
            #pragma unroll
            for (int mt = 0; mt < 2; ++mt)
                #pragma unroll
                for (int nt = 0; nt < 4; ++nt)
                    #pragma unroll
                    for (int c = 0; c < 4; ++c) {
                        int lr = warp_m * 32 + mt * 16 + (c >> 1) * 8 + (lane >> 2);
                        int lc = warp_n * 32 + nt * 8 + (lane & 3) * 2 + (c & 1);
                        if (lr == lc) rdiag[mt * 2 + (c >> 1)] += acc[mt][nt][c];
                    }
        }
    }

    // reduce: quad lanes share each row; then 4 n-warps per row via smem
    #pragma unroll
    for (int rs = 0; rs < 4; ++rs) {
        rsum[rs]  += __shfl_xor_sync(0xffffffffu, rsum[rs], 1);
        rsum[rs]  += __shfl_xor_sync(0xffffffffu, rsum[rs], 2);
        rdiag[rs] += __shfl_xor_sync(0xffffffffu, rdiag[rs], 1);
        rdiag[rs] += __shfl_xor_sync(0xffffffffu, rdiag[rs], 2);
    }
    __syncthreads();                       // B buffers free now
    float* s_sum = (float*)Bs0;            // [BM][4]
    float* s_dg  = s_sum + BM * 4;
    if ((lane & 3) == 0) {
        #pragma unroll
        for (int rs = 0; rs < 4; ++rs) {
            int lr = warp_m * 32 + (rs >> 1) * 16 + (rs & 1) * 8 + (lane >> 2);
            s_sum[lr * 4 + warp_n] = rsum[rs];
            s_dg [lr * 4 + warp_n] = rdiag[rs];
        }
    }
    __syncthreads();
    if (tid < BM) {
        float s = 0.f, d = 0.f;
        #pragma unroll
        for (int w = 0; w < 4; ++w) { s += s_sum[tid * 4 + w]; d += s_dg[tid * 4 + w]; }
        int gr = qr0 + tid;
        g_psum [gr * KSPLIT + split] = s;
        g_pdiag[gr * KSPLIT + split] = d;
    }
}

// ---------------------------------------------------------------------------
// Kernel 3: finalize. loss = mean( ln2 * (log2(sum splits) - diag_log2) )
// ---------------------------------------------------------------------------
__global__ void finalize_kernel(float* __restrict__ out) {
    __shared__ float wsum[8];
    float acc = 0.f;
    for (int r = blockIdx.x * 256 + threadIdx.x; r < NMAX; r += gridDim.x * 256) {
        float s = 0.f, d = 0.f;
        #pragma unroll
        for (int k = 0; k < KSPLIT; ++k) {
            s += g_psum [r * KSPLIT + k];
            d += g_pdiag[r * KSPLIT + k];
        }
        acc += LN2 * (log2f(s) - d);
    }
    #pragma unroll
    for (int o = 16; o > 0; o >>= 1) acc += __shfl_xor_sync(0xffffffffu, acc, o);
    if ((threadIdx.x & 31) == 0) wsum[threadIdx.x >> 5] = acc;
    __syncthreads();
    if (threadIdx.x == 0) {
        float t = 0.f;
        #pragma unroll
        for (int i = 0; i < 8; ++i) t += wsum[i];
        atomicAdd(out, t / (float)NMAX);
    }
}

// ---------------------------------------------------------------------------
extern "C" void kernel_launch(void* const* d_in, const int* in_sizes, int n_in,
                              void* d_out, int out_size) {
    const float* q = (const float*)d_in[0];
    const float* k = (const float*)d_in[1];
    const int N = in_sizes[0] / D;          // 8192
    float* out = (float*)d_out;

    cudaMemsetAsync(out, 0, sizeof(float), 0);   // atomicAdd accumulator

    normalize_kernel<<<2 * N / 8, 256>>>(q, k, N);

    size_t smem = (size_t)(BM + 2 * BN) * SPAD * sizeof(__nv_bfloat16);
    cudaFuncSetAttribute(infonce_kernel,
                         cudaFuncAttributeMaxDynamicSharedMemorySize, (int)smem);
    infonce_kernel<<<GRID_SZ, THREADS, smem>>>();

    finalize_kernel<<<16, 256>>>(out);
}

// round 7
// speedup vs baseline: 1.7143x; 1.1169x over previous
#include <cuda_runtime.h>
#include <cuda_bf16.h>
#include <cstdint>

#define D        256
#define NMAX     8192
#define BM       128
#define BN       128
#define KSPLIT   2
#define NKEYS    (NMAX / KSPLIT)         // 4096 keys per CTA
#define NT       (NKEYS / BN)            // 32 key tiles
#define GRID_SZ  ((NMAX / BM) * KSPLIT)  // 128 CTAs, one wave
#define THREADS  512
#define SPAD     264                     // 256 + 8 halves pad: conflict-free LDSM

#define LOG2E    1.4426950408889634f
#define LN2      0.6931471805599453f

// smem: [0..31] mbarriers (full0, full1, empty0, empty1), data from 128
#define MB_FULL0   0
#define MB_FULL1   8
#define MB_EMPTY0  16
#define MB_EMPTY1  24
#define DATA_OFF   128

__device__ __align__(16) __nv_bfloat16 g_Qn[(size_t)NMAX * D];
__device__ __align__(16) __nv_bfloat16 g_Kn[(size_t)NMAX * D];
__device__ float g_psum[NMAX * KSPLIT];
__device__ float g_pdiag[NMAX * KSPLIT];

// ---------------- helpers ----------------
__device__ __forceinline__ void cp_async16(void* smem_dst, const void* gmem_src) {
    uint32_t s = (uint32_t)__cvta_generic_to_shared(smem_dst);
    asm volatile("cp.async.cg.shared.global [%0], [%1], 16;\n" :: "r"(s), "l"(gmem_src));
}
// .noinc: one REAL arrival per thread (init count == #threads). The default
// (inc) form self-balances (+1 at issue, -1 at completion) and the barrier
// would never flip -> Round 6's deadlock.
__device__ __forceinline__ void cp_mbar_arrive_noinc(uint32_t mbar) {
    asm volatile("cp.async.mbarrier.arrive.noinc.shared::cta.b64 [%0];"
                 :: "r"(mbar) : "memory");
}
__device__ __forceinline__ void mbar_init(uint32_t a, uint32_t cnt) {
    asm volatile("mbarrier.init.shared.b64 [%0], %1;" :: "r"(a), "r"(cnt) : "memory");
}
__device__ __forceinline__ void mbar_arrive(uint32_t a) {
    asm volatile("mbarrier.arrive.shared.b64 _, [%0];" :: "r"(a) : "memory");
}
__device__ __forceinline__ void mbar_wait(uint32_t a, uint32_t parity) {
    asm volatile("{\n\t.reg .pred P1;\n\t"
                 "WAIT_LOOP_%=:\n\t"
                 "mbarrier.try_wait.parity.acquire.cta.shared::cta.b64 P1, [%0], %1, 0x989680;\n\t"
                 "@P1 bra.uni WAIT_DONE_%=;\n\t"
                 "bra.uni WAIT_LOOP_%=;\n\t"
                 "WAIT_DONE_%=:\n\t}" :: "r"(a), "r"(parity) : "memory");
}
__device__ __forceinline__ void ldsm_x4(uint32_t& r0, uint32_t& r1,
                                        uint32_t& r2, uint32_t& r3, uint32_t addr) {
    asm volatile("ldmatrix.sync.aligned.m8n8.x4.shared.b16 {%0,%1,%2,%3}, [%4];"
                 : "=r"(r0), "=r"(r1), "=r"(r2), "=r"(r3) : "r"(addr));
}
__device__ __forceinline__ float exp2_fast(float x) {
    float r;
    asm("ex2.approx.ftz.f32 %0, %1;" : "=f"(r) : "f"(x));
    return r;
}

// Load one [128 x 256 bf16] tile into SPAD-padded smem via cp.async (512 thr).
__device__ __forceinline__ void load_tile_async(__nv_bfloat16* s,
                                                const __nv_bfloat16* g, int tid) {
    const uint4* src = (const uint4*)g;
    #pragma unroll
    for (int i = tid; i < BM * 32; i += THREADS) {   // 32 x 16B chunks per row
        int r = i >> 5, c = i & 31;
        cp_async16(s + r * SPAD + c * 8, src + r * 32 + c);
    }
}

// ---------------------------------------------------------------------------
// Kernel 1: L2 normalize; one warp per row; queries get 2*log2(e) folded in
// (log2-domain logits, |logit| <= 2.89 -> no max tracking anywhere).
// ---------------------------------------------------------------------------
__global__ void normalize_kernel(const float* __restrict__ q,
                                 const float* __restrict__ k, int N) {
    const int warp = threadIdx.x >> 5, lane = threadIdx.x & 31;
    const int row  = blockIdx.x * 8 + warp;          // grid = 2N/8
    const bool is_q = row < N;
    const int  r    = is_q ? row : row - N;
    const float4* src = (const float4*)((is_q ? q : k) + (size_t)r * D);
    uint4* dst = (uint4*)((is_q ? g_Qn : g_Kn) + (size_t)r * D);

    float4 v0 = src[lane * 2], v1 = src[lane * 2 + 1];
    float ss = v0.x*v0.x + v0.y*v0.y + v0.z*v0.z + v0.w*v0.w
             + v1.x*v1.x + v1.y*v1.y + v1.z*v1.z + v1.w*v1.w;
    #pragma unroll
    for (int o = 16; o > 0; o >>= 1) ss += __shfl_xor_sync(0xffffffffu, ss, o);

    float scale = rsqrtf(fmaxf(ss, 1e-24f));
    if (is_q) scale *= 2.0f * LOG2E;    // 1/temperature + log2 domain

    __nv_bfloat162 b0 = __float22bfloat162_rn({v0.x*scale, v0.y*scale});
    __nv_bfloat162 b1 = __float22bfloat162_rn({v0.z*scale, v0.w*scale});
    __nv_bfloat162 b2 = __float22bfloat162_rn({v1.x*scale, v1.y*scale});
    __nv_bfloat162 b3 = __float22bfloat162_rn({v1.z*scale, v1.w*scale});
    uint4 o;
    o.x = *(uint32_t*)&b0; o.y = *(uint32_t*)&b1;
    o.z = *(uint32_t*)&b2; o.w = *(uint32_t*)&b3;
    dst[lane] = o;
}

// ---------------------------------------------------------------------------
// Kernel 2: bf16 mma.sync GEMM + fused sum(2^logit). 512 thr (16 warps),
// warp grid 4x4, warp tile 32x32, mma m16n8k16 via ldmatrix.
// mbarrier-paced double buffer: NO __syncthreads in the loop, so each warp's
// MUFU epilogue of tile t overlaps other warps' MMA of tile t+1.
// ---------------------------------------------------------------------------
__global__ __launch_bounds__(THREADS, 1)
void infonce_kernel() {
    extern __shared__ __align__(16) char smem_raw[];
    const uint32_t sb = (uint32_t)__cvta_generic_to_shared(smem_raw);
    __nv_bfloat16* As  = (__nv_bfloat16*)(smem_raw + DATA_OFF); // 128 * SPAD
    __nv_bfloat16* Bs0 = As + BM * SPAD;                        // buf 0
    __nv_bfloat16* Bs1 = Bs0 + BN * SPAD;                       // buf 1
    __nv_bfloat16* Bbuf[2] = { Bs0, Bs1 };

    const uint32_t full_mb[2]  = { sb + MB_FULL0,  sb + MB_FULL1 };
    const uint32_t empty_mb[2] = { sb + MB_EMPTY0, sb + MB_EMPTY1 };

    const int tid    = threadIdx.x;
    const int lane   = tid & 31;
    const int warp   = tid >> 5;
    const int warp_m = warp >> 2;       // 0..3 (32 rows each)
    const int warp_n = warp & 3;        // 0..3 (32 cols each)

    const int qb    = blockIdx.x / KSPLIT;
    const int split = blockIdx.x % KSPLIT;
    const int qr0   = qb * BM;
    const int kv0   = split * NKEYS;

    if (tid == 0) {
        mbar_init(full_mb[0], THREADS);  mbar_init(full_mb[1], THREADS);
        mbar_init(empty_mb[0], 16);      mbar_init(empty_mb[1], 16);
    }
    __syncthreads();

    // prologue: A + tile0 -> buf0, arrive on full[0] when this thread's cps land
    load_tile_async(As, g_Qn + (size_t)qr0 * D, tid);
    load_tile_async(Bs0, g_Kn + (size_t)kv0 * D, tid);
    cp_mbar_arrive_noinc(full_mb[0]);

    // ldmatrix addresses
    uint32_t a_base[2];
    #pragma unroll
    for (int mt = 0; mt < 2; ++mt)
        a_base[mt] = (uint32_t)__cvta_generic_to_shared(
            As + (warp_m * 32 + mt * 16 + (lane & 15)) * SPAD + (lane >> 4) * 8);
    uint32_t b_row_off[2];
    #pragma unroll
    for (int b = 0; b < 2; ++b)
        b_row_off[b] = (uint32_t)(
            ((warp_n * 32 + b * 16 + ((lane >> 4) & 1) * 8 + (lane & 7)) * SPAD
             + ((lane >> 3) & 1) * 8) * sizeof(__nv_bfloat16));

    const bool cta_has_diag = (qr0 >= kv0) && (qr0 < kv0 + NKEYS);
    const int  kt_diag      = (qr0 - kv0) >> 7;

    // phase parities: full waits start {0,0}; empty waits start {0,1}
    // (buf1's first write = tile1, free pass; buf0's first in-loop write = tile2)
    uint32_t cf0 = 0, cf1 = 0, pe0 = 0, pe1 = 1;

    float rsum[4]  = {0.f, 0.f, 0.f, 0.f};
    float rdiag[4] = {0.f, 0.f, 0.f, 0.f};

    for (int kt = 0; kt < NT; ++kt) {
        const int b  = kt & 1;
        const int nb = b ^ 1;

        // producer: prefetch tile kt+1 into buf nb (wait all warps' MMA(kt-1))
        if (kt + 1 < NT) {
            uint32_t pe = nb ? pe1 : pe0;
            mbar_wait(empty_mb[nb], pe);
            if (nb) pe1 ^= 1; else pe0 ^= 1;
            load_tile_async(Bbuf[nb], g_Kn + (size_t)(kv0 + (kt + 1) * BN) * D, tid);
            cp_mbar_arrive_noinc(full_mb[nb]);
        }

        // consumer: tile kt data fully visible
        {
            uint32_t cf = b ? cf1 : cf0;
            mbar_wait(full_mb[b], cf);
            if (b) cf1 ^= 1; else cf0 ^= 1;
        }

        float acc[2][4][4];
        #pragma unroll
        for (int a = 0; a < 2; ++a)
            #pragma unroll
            for (int bb2 = 0; bb2 < 4; ++bb2)
                #pragma unroll
                for (int c = 0; c < 4; ++c) acc[a][bb2][c] = 0.f;

        const uint32_t bb = (uint32_t)__cvta_generic_to_shared(Bbuf[b]);

        #pragma unroll
        for (int ks = 0; ks < D / 16; ++ks) {
            uint32_t af[2][4], bf[8];
            ldsm_x4(af[0][0], af[0][1], af[0][2], af[0][3], a_base[0] + ks * 32);
            ldsm_x4(af[1][0], af[1][1], af[1][2], af[1][3], a_base[1] + ks * 32);
            ldsm_x4(bf[0], bf[1], bf[2], bf[3], bb + b_row_off[0] + ks * 32);
            ldsm_x4(bf[4], bf[5], bf[6], bf[7], bb + b_row_off[1] + ks * 32);
            #pragma unroll
            for (int mt = 0; mt < 2; ++mt)
                #pragma unroll
                for (int nt = 0; nt < 4; ++nt) {
                    asm volatile(
                        "mma.sync.aligned.m16n8k16.row.col.f32.bf16.bf16.f32 "
                        "{%0,%1,%2,%3}, {%4,%5,%6,%7}, {%8,%9}, {%0,%1,%2,%3};\n"
                        : "+f"(acc[mt][nt][0]), "+f"(acc[mt][nt][1]),
                          "+f"(acc[mt][nt][2]), "+f"(acc[mt][nt][3])
                        : "r"(af[mt][0]), "r"(af[mt][1]),
                          "r"(af[mt][2]), "r"(af[mt][3]),
                          "r"(bf[nt * 2]), "r"(bf[nt * 2 + 1]));
                }
        }

        // done reading buf b -> let producers overwrite it (before epilogue!)
        if (lane == 0) mbar_arrive(empty_mb[b]);

        // epilogue: 32 ex2 + adds, register-only, overlaps others' MMA(kt+1)
        #pragma unroll
        for (int mt = 0; mt < 2; ++mt)
            #pragma unroll
            for (int nt = 0; nt < 4; ++nt)
                #pragma unroll
                for (int c = 0; c < 4; ++c)
                    rsum[mt * 2 + (c >> 1)] += exp2_fast(acc[mt][nt][c]);

        if (cta_has_diag && kt == kt_diag) {
            #pragma unroll
            for (int mt = 0; mt < 2; ++mt)
                #pragma unroll
                for (int nt = 0; nt < 4; ++nt)
                    #pragma unroll
                    for (int c = 0; c < 4; ++c) {
                        int lr = warp_m * 32 + mt * 16 + (c >> 1) * 8 + (lane >> 2);
                        int lc = warp_n * 32 + nt * 8 + (lane & 3) * 2 + (c & 1);
                        if (lr == lc) rdiag[mt * 2 + (c >> 1)] += acc[mt][nt][c];
                    }
        }
    }

    // reduce: quad lanes share each row; then 4 n-warps per row via smem
    #pragma unroll
    for (int rs = 0; rs < 4; ++rs) {
        rsum[rs]  += __shfl_xor_sync(0xffffffffu, rsum[rs], 1);
        rsum[rs]  += __shfl_xor_sync(0xffffffffu, rsum[rs], 2);
        rdiag[rs] += __shfl_xor_sync(0xffffffffu, rdiag[rs], 1);
        rdiag[rs] += __shfl_xor_sync(0xffffffffu, rdiag[rs], 2);
    }
    __syncthreads();                       // B buffers free now
    float* s_sum = (float*)Bs0;            // [BM][4]
    float* s_dg  = s_sum + BM * 4;
    if ((lane & 3) == 0) {
        #pragma unroll
        for (int rs = 0; rs < 4; ++rs) {
            int lr = warp_m * 32 + (rs >> 1) * 16 + (rs & 1) * 8 + (lane >> 2);
            s_sum[lr * 4 + warp_n] = rsum[rs];
            s_dg [lr * 4 + warp_n] = rdiag[rs];
        }
    }
    __syncthreads();
    if (tid < BM) {
        float s = 0.f, d = 0.f;
        #pragma unroll
        for (int w = 0; w < 4; ++w) { s += s_sum[tid * 4 + w]; d += s_dg[tid * 4 + w]; }
        int gr = qr0 + tid;
        g_psum [gr * KSPLIT + split] = s;
        g_pdiag[gr * KSPLIT + split] = d;
    }
}

// ---------------------------------------------------------------------------
// Kernel 3: finalize. loss = mean( ln2 * (log2(sum splits) - diag_log2) )
// ---------------------------------------------------------------------------
__global__ void finalize_kernel(float* __restrict__ out) {
    __shared__ float wsum[8];
    float acc = 0.f;
    for (int r = blockIdx.x * 256 + threadIdx.x; r < NMAX; r += gridDim.x * 256) {
        float s = 0.f, d = 0.f;
        #pragma unroll
        for (int k = 0; k < KSPLIT; ++k) {
            s += g_psum [r * KSPLIT + k];
            d += g_pdiag[r * KSPLIT + k];
        }
        acc += LN2 * (log2f(s) - d);
    }
    #pragma unroll
    for (int o = 16; o > 0; o >>= 1) acc += __shfl_xor_sync(0xffffffffu, acc, o);
    if ((threadIdx.x & 31) == 0) wsum[threadIdx.x >> 5] = acc;
    __syncthreads();
    if (threadIdx.x == 0) {
        float t = 0.f;
        #pragma unroll
        for (int i = 0; i < 8; ++i) t += wsum[i];
        atomicAdd(out, t / (float)NMAX);
    }
}

// ---------------------------------------------------------------------------
extern "C" void kernel_launch(void* const* d_in, const int* in_sizes, int n_in,
                              void* d_out, int out_size) {
    const float* q = (const float*)d_in[0];
    const float* k = (const float*)d_in[1];
    const int N = in_sizes[0] / D;          // 8192
    float* out = (float*)d_out;

    cudaMemsetAsync(out, 0, sizeof(float), 0);   // atomicAdd accumulator

    normalize_kernel<<<2 * N / 8, 256>>>(q, k, N);

    size_t smem = DATA_OFF + (size_t)(BM + 2 * BN) * SPAD * sizeof(__nv_bfloat16);
    cudaFuncSetAttribute(infonce_kernel,
                         cudaFuncAttributeMaxDynamicSharedMemorySize, (int)smem);
    infonce_kernel<<<GRID_SZ, THREADS, smem>>>();

    finalize_kernel<<<16, 256>>>(out);
}